// round 12
// baseline (speedup 1.0000x reference)
#include <cuda_runtime.h>

// Problem constants (B=32, T=1024, N=2048)
#define BB 32
#define TT 1024
#define NN 2048
#define ALPHA 0.995f
#define VTH   2.0f
#define SEG   16          // T-segments for k_grad_partial
#define TSEG  (TT / SEG)  // 64 timesteps per segment

#define SCAN_CTAS 1024    // k_scan grid: 32 scan + 992 prefetch CTAs
#define PF_ITERS  5       // per prefetch CTA: 5 x 16KB = 80KB; total ~77.5MB < L2

// Scratch (device globals -- no allocation allowed)
__device__ float g_S[BB * TT];   // S[b][t] = x[b,t,:] . w
__device__ float g_A[BB * TT];   // a[b][t] = v_t + q_t
__device__ float g_V2[BB];       // sum of v_t^2 per batch

// ---------------------------------------------------------------------------
// Kernel 1: S[b,t] = x[b,t,:] . w   (row dot products), [b][t] layout.
// grid = 4096 CTAs x 8 rows each, block = 128 threads, float4 loads.
// Measured ~6.15 TB/s -- at the read-stream HBM ceiling, unchanged.
// ---------------------------------------------------------------------------
__global__ __launch_bounds__(128) void k_gemv(const float4* __restrict__ X4,
                                              const float4* __restrict__ W4) {
    __shared__ float red[4];
    const int tid = threadIdx.x;

    const float4 w0 = W4[tid];
    const float4 w1 = W4[128 + tid];
    const float4 w2 = W4[256 + tid];
    const float4 w3 = W4[384 + tid];

    const int base_row = blockIdx.x * 8;

#pragma unroll 1
    for (int rr = 0; rr < 8; rr++) {
        const int r = base_row + rr;                 // r = b*TT + t
        const float4* xp = X4 + (size_t)r * (NN / 4);
        const float4 x0 = xp[tid];
        const float4 x1 = xp[128 + tid];
        const float4 x2 = xp[256 + tid];
        const float4 x3 = xp[384 + tid];

        float s = x0.x * w0.x + x0.y * w0.y + x0.z * w0.z + x0.w * w0.w
                + x1.x * w1.x + x1.y * w1.y + x1.z * w1.z + x1.w * w1.w
                + x2.x * w2.x + x2.y * w2.y + x2.z * w2.z + x2.w * w2.w
                + x3.x * w3.x + x3.y * w3.y + x3.z * w3.z + x3.w * w3.w;

#pragma unroll
        for (int o = 16; o > 0; o >>= 1)
            s += __shfl_xor_sync(0xFFFFFFFFu, s, o);
        if ((tid & 31) == 0) red[tid >> 5] = s;
        __syncthreads();
        if (tid == 0) g_S[r] = red[0] + red[1] + red[2] + red[3];
        __syncthreads();
    }
}

// ---------------------------------------------------------------------------
// Kernel 2: CTAs 0..31 run the per-batch scalar scans (smem-resident);
// CTAs 32..1023 prefetch a BOUNDED 77.5MB low-batch slice of X into L2
// for k_grad (complementary to what k_gemv's last wave leaves resident).
// Scan CTAs also zero the grad region of d_out (atomic targets).
// ---------------------------------------------------------------------------
__global__ __launch_bounds__(128) void k_scan(const float4* __restrict__ X4,
                                              const float* __restrict__ w,
                                              float* __restrict__ out) {
    __shared__ float sv[TT];   // holds s, then v in place
    __shared__ float sa[TT];   // a_t
    __shared__ float s_ww;
    const int tid = threadIdx.x;
    const int g   = blockIdx.x;

    if (g >= BB) {
        // ---- bounded L2 prefetch: CTA p covers 80KB starting at p*80KB ----
        const int p = g - BB;                       // 0..991
        const char* base = (const char*)X4 + (size_t)p * (PF_ITERS * 16384);
#pragma unroll
        for (int it = 0; it < PF_ITERS; it++) {
            const char* ptr = base + it * 16384 + tid * 128;
            asm volatile("prefetch.global.L2 [%0];" :: "l"(ptr));
        }
        return;
    }

    const int b = g;
    const float* srow = g_S + b * TT;
    for (int t = tid; t < TT; t += 128) sv[t] = srow[t];

    // zero this batch's grad slice (coalesced float4 stores)
    {
        float4* gz = (float4*)(out + 2 * BB * TT + b * NN);
#pragma unroll
        for (int i = tid; i < NN / 4; i += 128)
            gz[i] = make_float4(0.f, 0.f, 0.f, 0.f);
    }

    if (tid < 32) {
        float ww = 0.0f;
#pragma unroll 8
        for (int i = tid; i < NN; i += 32) ww += w[i] * w[i];
#pragma unroll
        for (int o = 16; o > 0; o >>= 1)
            ww += __shfl_xor_sync(0xFFFFFFFFu, ww, o);
        if (tid == 0) s_ww = ww;
    }
    __syncthreads();

    if (tid == 0) {
        const float ww = s_ww;

        // ---- forward scan: v_t = a*v_{t-1} + s_t - VTH*z_{t-1} ----
        float v = 0.0f, v2 = 0.0f;
#pragma unroll 8
        for (int t = 0; t < TT; t++) {
            const float s   = sv[t];
            const float sub = (v > VTH) ? VTH : 0.0f;  // pred-as-data FSEL
            v = fmaf(ALPHA, v, s) - sub;
            sv[t] = v;
            v2 += v * v;                               // off-chain
        }
        g_V2[b] = v2;

        // ---- backward scan: c_t reconstructed from v values ----
        float q = 0.0f;
#pragma unroll 8
        for (int t = TT - 1; t > 0; t--) {
            const float vt = sv[t];
            const float vp = sv[t - 1];
            sa[t] = vt + q;                                  // a_t = v_t + q_t
            const float zc = (vp > VTH) ? VTH : 0.0f;
            const float c  = vt - ALPHA * vp - vt * ww + zc; // off-chain
            q = fmaf(ALPHA, q, c);                           // 4cy FFMA chain
        }
        sa[0] = sv[0] + q;
    }
    __syncthreads();

    float* vout = out + b * TT;
    float* zout = out + BB * TT + b * TT;
    float* aout = g_A + b * TT;
    for (int t = tid; t < TT; t += 128) {
        const float v = sv[t];
        vout[t] = v;
        zout[t] = (v > VTH) ? 1.0f : 0.0f;
        aout[t] = sa[t];
    }
}

// ---------------------------------------------------------------------------
// Kernel 3: partial grad over a T-segment, accumulated into d_out via RED.
//   grad[b][n] += sum_{t in seg} a[b,t] * x[b,t,n]   (- V2[b]*w[n] on seg 0)
// grid = (4 chunks, 32 b, SEG) = 2048 CTAs, block = 128 threads.
// Per-row footprint per CTA: 128 threads x 16B = 2048 B contiguous.
// ---------------------------------------------------------------------------
__global__ __launch_bounds__(128) void k_grad_partial(const float4* __restrict__ X4,
                                                      const float4* __restrict__ W4,
                                                      float* __restrict__ out) {
    __shared__ float sa[TSEG];
    const int tid   = threadIdx.x;   // 0..127
    const int chunk = blockIdx.x;    // 0..3
    const int b     = blockIdx.y;    // 0..31
    const int seg   = blockIdx.z;    // 0..SEG-1
    const int t0    = seg * TSEG;

    if (tid < TSEG) sa[tid] = g_A[b * TT + t0 + tid];
    __syncthreads();

    const int col4 = chunk * 128 + tid;  // float4 column index, 0..511
    const float4* xp = X4 + ((size_t)b * TT + t0) * (NN / 4) + col4;

    float4 acc = make_float4(0.f, 0.f, 0.f, 0.f);
#pragma unroll 8
    for (int t = 0; t < TSEG; t++) {
        const float a = sa[t];
        const float4 x = xp[(size_t)t * (NN / 4)];
        acc.x += a * x.x;
        acc.y += a * x.y;
        acc.z += a * x.z;
        acc.w += a * x.w;
    }

    if (seg == 0) {  // fold in -V2[b]*w[n] exactly once
        const float v2 = g_V2[b];
        const float4 wv = W4[col4];
        acc.x -= v2 * wv.x;
        acc.y -= v2 * wv.y;
        acc.z -= v2 * wv.z;
        acc.w -= v2 * wv.w;
    }

    float* gout = out + 2 * BB * TT + b * NN + col4 * 4;
    atomicAdd(gout + 0, acc.x);   // RED.E.ADD.F32 (no return)
    atomicAdd(gout + 1, acc.y);
    atomicAdd(gout + 2, acc.z);
    atomicAdd(gout + 3, acc.w);
}

// ---------------------------------------------------------------------------
extern "C" void kernel_launch(void* const* d_in, const int* in_sizes, int n_in,
                              void* d_out, int out_size) {
    const float* x = (const float*)d_in[0];
    const float* w = (const float*)d_in[1];
    if (n_in >= 2 && in_sizes[0] == NN && in_sizes[1] != NN) {
        const float* tmp = x; x = w; w = tmp;
    }
    float* out = (float*)d_out;

    k_gemv<<<4096, 128>>>((const float4*)x, (const float4*)w);
    k_scan<<<SCAN_CTAS, 128>>>((const float4*)x, w, out);
    k_grad_partial<<<dim3(4, 32, SEG), 128>>>((const float4*)x, (const float4*)w, out);
}

// round 13
// speedup vs baseline: 1.0059x; 1.0059x over previous
#include <cuda_runtime.h>

// Problem constants (B=32, T=1024, N=2048)
#define BB 32
#define TT 1024
#define NN 2048
#define ALPHA 0.995f
#define VTH   2.0f
#define SEG   16          // T-segments for k_grad_partial
#define TSEG  (TT / SEG)  // 64 timesteps per segment

#define SCAN_CTAS 1024    // k_scan grid: 32 scan + 992 prefetch CTAs
#define PF_ITERS  5       // per prefetch CTA: 5 x 16KB = 80KB; total ~77.5MB < L2

// Scratch (device globals -- no allocation allowed)
__device__ float g_S[BB * TT];   // S[b][t] = x[b,t,:] . w
__device__ float g_A[BB * TT];   // a[b][t] = v_t + q_t
__device__ float g_V2[BB];       // sum of v_t^2 per batch

// ---------------------------------------------------------------------------
// Kernel 1: S[b,t] = x[b,t,:] . w   (row dot products), [b][t] layout.
// grid = 4096 CTAs x 8 rows each, block = 128 threads, float4 loads.
// Measured ~6.15 TB/s -- at the read-stream HBM ceiling, unchanged.
// ---------------------------------------------------------------------------
__global__ __launch_bounds__(128) void k_gemv(const float4* __restrict__ X4,
                                              const float4* __restrict__ W4) {
    __shared__ float red[4];
    const int tid = threadIdx.x;

    const float4 w0 = W4[tid];
    const float4 w1 = W4[128 + tid];
    const float4 w2 = W4[256 + tid];
    const float4 w3 = W4[384 + tid];

    const int base_row = blockIdx.x * 8;

#pragma unroll 1
    for (int rr = 0; rr < 8; rr++) {
        const int r = base_row + rr;                 // r = b*TT + t
        const float4* xp = X4 + (size_t)r * (NN / 4);
        const float4 x0 = xp[tid];
        const float4 x1 = xp[128 + tid];
        const float4 x2 = xp[256 + tid];
        const float4 x3 = xp[384 + tid];

        float s = x0.x * w0.x + x0.y * w0.y + x0.z * w0.z + x0.w * w0.w
                + x1.x * w1.x + x1.y * w1.y + x1.z * w1.z + x1.w * w1.w
                + x2.x * w2.x + x2.y * w2.y + x2.z * w2.z + x2.w * w2.w
                + x3.x * w3.x + x3.y * w3.y + x3.z * w3.z + x3.w * w3.w;

#pragma unroll
        for (int o = 16; o > 0; o >>= 1)
            s += __shfl_xor_sync(0xFFFFFFFFu, s, o);
        if ((tid & 31) == 0) red[tid >> 5] = s;
        __syncthreads();
        if (tid == 0) g_S[r] = red[0] + red[1] + red[2] + red[3];
        __syncthreads();
    }
}

// ---------------------------------------------------------------------------
// Kernel 2: CTAs 0..31 run the per-batch scalar scans (smem-resident);
// CTAs 32..1023 prefetch a BOUNDED 77.5MB low-batch slice of X into L2
// for k_grad (complementary to what k_gemv's last wave leaves resident).
// Scan CTAs also zero the grad region of d_out (atomic targets).
// ---------------------------------------------------------------------------
__global__ __launch_bounds__(128) void k_scan(const float4* __restrict__ X4,
                                              const float* __restrict__ w,
                                              float* __restrict__ out) {
    __shared__ float sv[TT];   // holds s, then v in place
    __shared__ float sa[TT];   // a_t
    __shared__ float s_ww;
    const int tid = threadIdx.x;
    const int g   = blockIdx.x;

    if (g >= BB) {
        // ---- bounded L2 prefetch: CTA p covers 80KB starting at p*80KB ----
        const int p = g - BB;                       // 0..991
        const char* base = (const char*)X4 + (size_t)p * (PF_ITERS * 16384);
#pragma unroll
        for (int it = 0; it < PF_ITERS; it++) {
            const char* ptr = base + it * 16384 + tid * 128;
            asm volatile("prefetch.global.L2 [%0];" :: "l"(ptr));
        }
        return;
    }

    const int b = g;
    const float* srow = g_S + b * TT;
    for (int t = tid; t < TT; t += 128) sv[t] = srow[t];

    // zero this batch's grad slice (coalesced float4 stores)
    {
        float4* gz = (float4*)(out + 2 * BB * TT + b * NN);
#pragma unroll
        for (int i = tid; i < NN / 4; i += 128)
            gz[i] = make_float4(0.f, 0.f, 0.f, 0.f);
    }

    if (tid < 32) {
        float ww = 0.0f;
#pragma unroll 8
        for (int i = tid; i < NN; i += 32) ww += w[i] * w[i];
#pragma unroll
        for (int o = 16; o > 0; o >>= 1)
            ww += __shfl_xor_sync(0xFFFFFFFFu, ww, o);
        if (tid == 0) s_ww = ww;
    }
    __syncthreads();

    if (tid == 0) {
        const float ww = s_ww;

        // ---- forward scan: v_t = a*v_{t-1} + s_t - VTH*z_{t-1} ----
        float v = 0.0f, v2 = 0.0f;
#pragma unroll 8
        for (int t = 0; t < TT; t++) {
            const float s   = sv[t];
            const float sub = (v > VTH) ? VTH : 0.0f;  // pred-as-data FSEL
            v = fmaf(ALPHA, v, s) - sub;
            sv[t] = v;
            v2 += v * v;                               // off-chain
        }
        g_V2[b] = v2;

        // ---- backward scan: c_t reconstructed from v values ----
        float q = 0.0f;
#pragma unroll 8
        for (int t = TT - 1; t > 0; t--) {
            const float vt = sv[t];
            const float vp = sv[t - 1];
            sa[t] = vt + q;                                  // a_t = v_t + q_t
            const float zc = (vp > VTH) ? VTH : 0.0f;
            const float c  = vt - ALPHA * vp - vt * ww + zc; // off-chain
            q = fmaf(ALPHA, q, c);                           // 4cy FFMA chain
        }
        sa[0] = sv[0] + q;
    }
    __syncthreads();

    float* vout = out + b * TT;
    float* zout = out + BB * TT + b * TT;
    float* aout = g_A + b * TT;
    for (int t = tid; t < TT; t += 128) {
        const float v = sv[t];
        vout[t] = v;
        zout[t] = (v > VTH) ? 1.0f : 0.0f;
        aout[t] = sa[t];
    }
}

// ---------------------------------------------------------------------------
// Kernel 3: partial grad over a T-segment, accumulated into d_out via RED.
//   grad[b][n] += sum_{t in seg} a[b,t] * x[b,t,n]   (- V2[b]*w[n] on seg 0)
// grid = (4 chunks, 32 b, SEG) = 2048 CTAs, block = 128 threads.
// Per-row footprint per CTA: 128 threads x 16B = 2048 B contiguous.
// ---------------------------------------------------------------------------
__global__ __launch_bounds__(128) void k_grad_partial(const float4* __restrict__ X4,
                                                      const float4* __restrict__ W4,
                                                      float* __restrict__ out) {
    __shared__ float sa[TSEG];
    const int tid   = threadIdx.x;   // 0..127
    const int chunk = blockIdx.x;    // 0..3
    const int b     = blockIdx.y;    // 0..31
    const int seg   = blockIdx.z;    // 0..SEG-1
    const int t0    = seg * TSEG;

    if (tid < TSEG) sa[tid] = g_A[b * TT + t0 + tid];
    __syncthreads();

    const int col4 = chunk * 128 + tid;  // float4 column index, 0..511
    const float4* xp = X4 + ((size_t)b * TT + t0) * (NN / 4) + col4;

    float4 acc = make_float4(0.f, 0.f, 0.f, 0.f);
#pragma unroll 8
    for (int t = 0; t < TSEG; t++) {
        const float a = sa[t];
        const float4 x = xp[(size_t)t * (NN / 4)];
        acc.x += a * x.x;
        acc.y += a * x.y;
        acc.z += a * x.z;
        acc.w += a * x.w;
    }

    if (seg == 0) {  // fold in -V2[b]*w[n] exactly once
        const float v2 = g_V2[b];
        const float4 wv = W4[col4];
        acc.x -= v2 * wv.x;
        acc.y -= v2 * wv.y;
        acc.z -= v2 * wv.z;
        acc.w -= v2 * wv.w;
    }

    float* gout = out + 2 * BB * TT + b * NN + col4 * 4;
    atomicAdd(gout + 0, acc.x);   // RED.E.ADD.F32 (no return)
    atomicAdd(gout + 1, acc.y);
    atomicAdd(gout + 2, acc.z);
    atomicAdd(gout + 3, acc.w);
}

// ---------------------------------------------------------------------------
extern "C" void kernel_launch(void* const* d_in, const int* in_sizes, int n_in,
                              void* d_out, int out_size) {
    const float* x = (const float*)d_in[0];
    const float* w = (const float*)d_in[1];
    if (n_in >= 2 && in_sizes[0] == NN && in_sizes[1] != NN) {
        const float* tmp = x; x = w; w = tmp;
    }
    float* out = (float*)d_out;

    k_gemv<<<4096, 128>>>((const float4*)x, (const float4*)w);
    k_scan<<<SCAN_CTAS, 128>>>((const float4*)x, w, out);
    k_grad_partial<<<dim3(4, 32, SEG), 128>>>((const float4*)x, (const float4*)w, out);
}

// round 14
// speedup vs baseline: 1.0392x; 1.0331x over previous
#include <cuda_runtime.h>

// Problem constants (B=32, T=1024, N=2048)
#define BB 32
#define TT 1024
#define NN 2048
#define ALPHA 0.995f
#define VTH   2.0f
#define SEG   16          // T-segments for k_grad_partial
#define TSEG  (TT / SEG)  // 64 timesteps per segment

// Scratch (device globals -- no allocation allowed)
__device__ float    g_S[BB * TT];   // S[b][t] = x[b,t,:] . w
__device__ float    g_A[BB * TT];   // a[b][t] = v_t + q_t
__device__ float    g_V2[BB];       // sum of v_t^2 per batch
__device__ unsigned g_cnt[BB];      // per-batch gemv completion (monotonic)

// ---------------------------------------------------------------------------
// Kernel 1 (fused): gemv + per-batch inline scan.
// grid = 4096 CTAs x 8 rows each; batch b is produced by CTAs [b*128,(b+1)*128).
// The CTA that completes its batch's counter runs that batch's scalar scans
// inline (overlapped with other CTAs' gemv work). Replay-safe: counters are
// monotonic, scanner = CTA whose increment makes count % 128 == 0.
// ---------------------------------------------------------------------------
__global__ __launch_bounds__(128) void k_gemv_scan(const float4* __restrict__ X4,
                                                   const float4* __restrict__ W4,
                                                   float* __restrict__ out) {
    __shared__ float red[4];
    __shared__ float sv[TT];      // scan: s then v in place
    __shared__ float sa[TT];      // scan: a_t
    __shared__ unsigned s_scan;
    const int tid = threadIdx.x;
    const int g   = blockIdx.x;

    const float4 w0 = W4[tid];
    const float4 w1 = W4[128 + tid];
    const float4 w2 = W4[256 + tid];
    const float4 w3 = W4[384 + tid];

    // zero the grad region of d_out (atomic targets for k_grad_partial)
    if (g < 64) {
        float4* gz = (float4*)(out + 2 * BB * TT) + g * 256;
        for (int i = tid; i < 256; i += 128)
            gz[i] = make_float4(0.f, 0.f, 0.f, 0.f);
    }

    const int base_row = g * 8;
    const int b = base_row >> 10;             // batch of all 8 rows

#pragma unroll 1
    for (int rr = 0; rr < 8; rr++) {
        const int r = base_row + rr;          // r = b*TT + t
        const float4* xp = X4 + (size_t)r * (NN / 4);
        const float4 x0 = xp[tid];
        const float4 x1 = xp[128 + tid];
        const float4 x2 = xp[256 + tid];
        const float4 x3 = xp[384 + tid];

        float s = x0.x * w0.x + x0.y * w0.y + x0.z * w0.z + x0.w * w0.w
                + x1.x * w1.x + x1.y * w1.y + x1.z * w1.z + x1.w * w1.w
                + x2.x * w2.x + x2.y * w2.y + x2.z * w2.z + x2.w * w2.w
                + x3.x * w3.x + x3.y * w3.y + x3.z * w3.z + x3.w * w3.w;

#pragma unroll
        for (int o = 16; o > 0; o >>= 1)
            s += __shfl_xor_sync(0xFFFFFFFFu, s, o);
        if ((tid & 31) == 0) red[tid >> 5] = s;
        __syncthreads();
        if (tid == 0) g_S[r] = red[0] + red[1] + red[2] + red[3];
        __syncthreads();
    }

    // ---- batch completion: last CTA of the batch becomes its scanner ----
    if (tid == 0) {
        __threadfence();
        const unsigned old = atomicAdd(&g_cnt[b], 1u);
        s_scan = (((old + 1u) & 127u) == 0u) ? 1u : 0u;
    }
    __syncthreads();
    if (!s_scan) return;
    __threadfence();   // acquire side: g_S writes of peer CTAs now visible

    // ---- w.w from the registers we already hold ----
    float ww = w0.x * w0.x + w0.y * w0.y + w0.z * w0.z + w0.w * w0.w
             + w1.x * w1.x + w1.y * w1.y + w1.z * w1.z + w1.w * w1.w
             + w2.x * w2.x + w2.y * w2.y + w2.z * w2.z + w2.w * w2.w
             + w3.x * w3.x + w3.y * w3.y + w3.z * w3.z + w3.w * w3.w;
#pragma unroll
    for (int o = 16; o > 0; o >>= 1)
        ww += __shfl_xor_sync(0xFFFFFFFFu, ww, o);
    if ((tid & 31) == 0) red[tid >> 5] = ww;

    // ---- load this batch's S row into smem (L2-hot, just written) ----
    const float* srow = g_S + b * TT;
    for (int t = tid; t < TT; t += 128) sv[t] = srow[t];
    __syncthreads();

    if (tid == 0) {
        const float wws = red[0] + red[1] + red[2] + red[3];

        // forward scan: v_t = a*v + s_t - VTH*z_{t-1}
        // z via saturate-step: exact step(v > VTH) incl. boundary; chain = 2 FFMA.
        float v = 0.0f, v2 = 0.0f;
#pragma unroll 8
        for (int t = 0; t < TT; t++) {
            const float s  = sv[t];
            const float z  = __saturatef(fmaf(v, 1e38f, -(VTH * 1e38f)));
            const float va = fmaf(ALPHA, v, s);
            v = fmaf(-VTH, z, va);
            sv[t] = v;
            v2 += v * v;                       // off-chain
        }
        g_V2[b] = v2;

        // backward scan: c_t reconstructed from v; q chain = single FFMA
        float q = 0.0f;
#pragma unroll 8
        for (int t = TT - 1; t > 0; t--) {
            const float vt = sv[t];
            const float vp = sv[t - 1];
            sa[t] = vt + q;                                    // a_t = v_t + q_t
            const float zc = VTH * __saturatef(fmaf(vp, 1e38f, -(VTH * 1e38f)));
            const float c  = vt - ALPHA * vp - vt * wws + zc;  // off-chain
            q = fmaf(ALPHA, q, c);
        }
        sa[0] = sv[0] + q;
    }
    __syncthreads();

    // epilogue: v_seq, z_seq (exact comparison), a
    float* vout = out + b * TT;
    float* zout = out + BB * TT + b * TT;
    float* aout = g_A + b * TT;
    for (int t = tid; t < TT; t += 128) {
        const float v = sv[t];
        vout[t] = v;
        zout[t] = (v > VTH) ? 1.0f : 0.0f;
        aout[t] = sa[t];
    }
}

// ---------------------------------------------------------------------------
// Kernel 2: partial grad over a T-segment, accumulated into d_out via RED.
//   grad[b][n] += sum_{t in seg} a[b,t] * x[b,t,n]   (- V2[b]*w[n] on seg 0)
// grid = (4 chunks, 32 b, SEG) = 2048 CTAs, block = 128 threads.
// Per-row footprint per CTA: 128 threads x 16B = 2048 B contiguous.
// ---------------------------------------------------------------------------
__global__ __launch_bounds__(128) void k_grad_partial(const float4* __restrict__ X4,
                                                      const float4* __restrict__ W4,
                                                      float* __restrict__ out) {
    __shared__ float sa[TSEG];
    const int tid   = threadIdx.x;   // 0..127
    const int chunk = blockIdx.x;    // 0..3
    const int b     = blockIdx.y;    // 0..31
    const int seg   = blockIdx.z;    // 0..SEG-1
    const int t0    = seg * TSEG;

    if (tid < TSEG) sa[tid] = g_A[b * TT + t0 + tid];
    __syncthreads();

    const int col4 = chunk * 128 + tid;  // float4 column index, 0..511
    const float4* xp = X4 + ((size_t)b * TT + t0) * (NN / 4) + col4;

    float4 acc = make_float4(0.f, 0.f, 0.f, 0.f);
#pragma unroll 8
    for (int t = 0; t < TSEG; t++) {
        const float a = sa[t];
        const float4 x = xp[(size_t)t * (NN / 4)];
        acc.x += a * x.x;
        acc.y += a * x.y;
        acc.z += a * x.z;
        acc.w += a * x.w;
    }

    if (seg == 0) {  // fold in -V2[b]*w[n] exactly once
        const float v2 = g_V2[b];
        const float4 wv = W4[col4];
        acc.x -= v2 * wv.x;
        acc.y -= v2 * wv.y;
        acc.z -= v2 * wv.z;
        acc.w -= v2 * wv.w;
    }

    float* gout = out + 2 * BB * TT + b * NN + col4 * 4;
    atomicAdd(gout + 0, acc.x);   // RED.E.ADD.F32 (no return)
    atomicAdd(gout + 1, acc.y);
    atomicAdd(gout + 2, acc.z);
    atomicAdd(gout + 3, acc.w);
}

// ---------------------------------------------------------------------------
extern "C" void kernel_launch(void* const* d_in, const int* in_sizes, int n_in,
                              void* d_out, int out_size) {
    const float* x = (const float*)d_in[0];
    const float* w = (const float*)d_in[1];
    if (n_in >= 2 && in_sizes[0] == NN && in_sizes[1] != NN) {
        const float* tmp = x; x = w; w = tmp;
    }
    float* out = (float*)d_out;

    k_gemv_scan<<<4096, 128>>>((const float4*)x, (const float4*)w, out);
    k_grad_partial<<<dim3(4, 32, SEG), 128>>>((const float4*)x, (const float4*)w, out);
}

// round 15
// speedup vs baseline: 1.1000x; 1.0585x over previous
#include <cuda_runtime.h>

// Problem constants (B=32, T=1024, N=2048)
#define BB 32
#define TT 1024
#define NN 2048
#define ALPHA 0.995f
#define VTH   2.0f
#define SEG   16            // grad T-segments
#define TSEG  (TT / SEG)    // 64 timesteps per segment
#define G_GEMV 4096         // gemv CTAs (8 rows each)
#define G_GRAD 2048         // grad CTAs (4 chunks x 32 b x 16 seg)

// Scratch (device globals -- no allocation allowed)
__device__ float    g_S[BB * TT];     // S[b][t]
__device__ float    g_A[BB * TT];     // a[b][t] = v_t + q_t
__device__ float    g_V2[BB];         // sum v_t^2
__device__ unsigned g_cnt[BB];        // per-batch gemv completion (monotonic)
__device__ unsigned g_scan_done[BB];  // per-batch scan epoch (monotonic)
__device__ unsigned g_grad_arrive;    // grad-CTA arrivals (monotonic)

__global__ __launch_bounds__(128) void k_all(const float4* __restrict__ X4,
                                             const float4* __restrict__ W4,
                                             float* __restrict__ out) {
    __shared__ float sv[TT];      // gemv/scan: s then v in place
    __shared__ float sa[TT];      // scan: a_t ; grad: sa[0:TSEG]
    __shared__ float red[4];
    __shared__ unsigned s_u;
    const int tid = threadIdx.x;
    const int g   = blockIdx.x;

    if (g < G_GEMV) {
        // ================= gemv (+ inline scan for the batch finisher) =====
        const float4 w0 = W4[tid];
        const float4 w1 = W4[128 + tid];
        const float4 w2 = W4[256 + tid];
        const float4 w3 = W4[384 + tid];

        const int base_row = g * 8;
        const int b    = base_row >> 10;     // batch of all 8 rows
        const int gloc = g & 127;            // position within batch group

        // first 2 CTAs of each batch group zero that batch's grad slice
        if (gloc < 2) {
            float4* gz = (float4*)(out + 2 * BB * TT + b * NN) + gloc * 256;
#pragma unroll
            for (int i = tid; i < 256; i += 128)
                gz[i] = make_float4(0.f, 0.f, 0.f, 0.f);
        }

#pragma unroll 1
        for (int rr = 0; rr < 8; rr++) {
            const int r = base_row + rr;                 // r = b*TT + t
            const float4* xp = X4 + (size_t)r * (NN / 4);
            const float4 x0 = xp[tid];
            const float4 x1 = xp[128 + tid];
            const float4 x2 = xp[256 + tid];
            const float4 x3 = xp[384 + tid];

            float s = x0.x * w0.x + x0.y * w0.y + x0.z * w0.z + x0.w * w0.w
                    + x1.x * w1.x + x1.y * w1.y + x1.z * w1.z + x1.w * w1.w
                    + x2.x * w2.x + x2.y * w2.y + x2.z * w2.z + x2.w * w2.w
                    + x3.x * w3.x + x3.y * w3.y + x3.z * w3.z + x3.w * w3.w;

#pragma unroll
            for (int o = 16; o > 0; o >>= 1)
                s += __shfl_xor_sync(0xFFFFFFFFu, s, o);
            if ((tid & 31) == 0) red[tid >> 5] = s;
            __syncthreads();
            if (tid == 0) g_S[r] = red[0] + red[1] + red[2] + red[3];
            __syncthreads();
        }

        // ---- batch completion: the finisher becomes the scanner ----
        if (tid == 0) {
            __threadfence();
            const unsigned old = atomicAdd(&g_cnt[b], 1u);
            s_u = (((old + 1u) & 127u) == 0u) ? 1u : 0u;
        }
        __syncthreads();
        if (!s_u) return;
        __threadfence();   // acquire: peer CTAs' g_S writes visible

        // ---- w.w from registers already held ----
        float ww = w0.x * w0.x + w0.y * w0.y + w0.z * w0.z + w0.w * w0.w
                 + w1.x * w1.x + w1.y * w1.y + w1.z * w1.z + w1.w * w1.w
                 + w2.x * w2.x + w2.y * w2.y + w2.z * w2.z + w2.w * w2.w
                 + w3.x * w3.x + w3.y * w3.y + w3.z * w3.z + w3.w * w3.w;
#pragma unroll
        for (int o = 16; o > 0; o >>= 1)
            ww += __shfl_xor_sync(0xFFFFFFFFu, ww, o);
        if ((tid & 31) == 0) red[tid >> 5] = ww;

        const float* srow = g_S + b * TT;
        for (int t = tid; t < TT; t += 128) sv[t] = srow[t];
        __syncthreads();

        if (tid == 0) {
            const float wws = red[0] + red[1] + red[2] + red[3];

            // forward: v_t = a*v + s_t - VTH*z_{t-1}; z via exact saturate-step
            float v = 0.0f, v2 = 0.0f;
#pragma unroll 8
            for (int t = 0; t < TT; t++) {
                const float s  = sv[t];
                const float z  = __saturatef(fmaf(v, 1e38f, -(VTH * 1e38f)));
                const float va = fmaf(ALPHA, v, s);
                v = fmaf(-VTH, z, va);
                sv[t] = v;
                v2 += v * v;
            }
            g_V2[b] = v2;

            // backward: c_t reconstructed from v; q chain = single FFMA
            float q = 0.0f;
#pragma unroll 8
            for (int t = TT - 1; t > 0; t--) {
                const float vt = sv[t];
                const float vp = sv[t - 1];
                sa[t] = vt + q;
                const float zc = VTH * __saturatef(fmaf(vp, 1e38f, -(VTH * 1e38f)));
                const float c  = vt - ALPHA * vp - vt * wws + zc;
                q = fmaf(ALPHA, q, c);
            }
            sa[0] = sv[0] + q;
        }
        __syncthreads();

        float* vout = out + b * TT;
        float* zout = out + BB * TT + b * TT;
        float* aout = g_A + b * TT;
        for (int t = tid; t < TT; t += 128) {
            const float v = sv[t];
            vout[t] = v;
            zout[t] = (v > VTH) ? 1.0f : 0.0f;
            aout[t] = sa[t];
        }

        // release: this batch's a / V2 / grad-zero are ready
        if (tid == 0) {
            __threadfence();
            atomicAdd(&g_scan_done[b], 1u);
        }
        return;
    }

    // ===================== grad CTA ========================================
    const int g2    = g - G_GEMV;        // 0..2047
    const int b     = g2 >> 6;           // 64 CTAs per batch
    const int rem   = g2 & 63;
    const int chunk = rem & 3;           // 0..3
    const int seg   = rem >> 2;          // 0..15
    const int t0    = seg * TSEG;

    // replay-safe epoch + per-batch spin (release/acquire via L2)
    if (tid == 0) {
        const unsigned old = atomicAdd(&g_grad_arrive, 1u);
        const unsigned target = old / G_GRAD + 1u;
        while (*(volatile unsigned*)&g_scan_done[b] < target) __nanosleep(64);
    }
    __syncthreads();
    __threadfence();

    if (tid < TSEG) sa[tid] = __ldcg(&g_A[b * TT + t0 + tid]);
    __syncthreads();

    const int col4 = chunk * 128 + tid;  // float4 column index, 0..511
    const float4* xp = X4 + ((size_t)b * TT + t0) * (NN / 4) + col4;

    float4 acc = make_float4(0.f, 0.f, 0.f, 0.f);
#pragma unroll 8
    for (int t = 0; t < TSEG; t++) {
        const float a = sa[t];
        const float4 x = xp[(size_t)t * (NN / 4)];
        acc.x += a * x.x;
        acc.y += a * x.y;
        acc.z += a * x.z;
        acc.w += a * x.w;
    }

    if (seg == 0) {  // fold in -V2[b]*w[n] exactly once
        const float v2 = __ldcg(&g_V2[b]);
        const float4 wv = W4[col4];
        acc.x -= v2 * wv.x;
        acc.y -= v2 * wv.y;
        acc.z -= v2 * wv.z;
        acc.w -= v2 * wv.w;
    }

    float* gout = out + 2 * BB * TT + b * NN + col4 * 4;
    atomicAdd(gout + 0, acc.x);   // RED.E.ADD.F32 (no return)
    atomicAdd(gout + 1, acc.y);
    atomicAdd(gout + 2, acc.z);
    atomicAdd(gout + 3, acc.w);
}

// ---------------------------------------------------------------------------
extern "C" void kernel_launch(void* const* d_in, const int* in_sizes, int n_in,
                              void* d_out, int out_size) {
    const float* x = (const float*)d_in[0];
    const float* w = (const float*)d_in[1];
    if (n_in >= 2 && in_sizes[0] == NN && in_sizes[1] != NN) {
        const float* tmp = x; x = w; w = tmp;
    }
    float* out = (float*)d_out;

    k_all<<<G_GEMV + G_GRAD, 128>>>((const float4*)x, (const float4*)w, out);
}